// round 2
// baseline (speedup 1.0000x reference)
#include <cuda_runtime.h>

#define SEQ   8192
#define DIM   128
#define GATES 512
#define TOK_PER_BLK 8
#define WSM_STRIDE  68   // 64 used cols + 4 pad -> conflict-free LDS.128 at stride 68 floats
#define SMEM_FLOATS (GATES * WSM_STRIDE + GATES + 132)

// Scratch (device globals; no runtime allocation allowed)
__device__ float g_z[SEQ * DIM];        // expert-linear output, 4 MB
__device__ float g_xg[SEQ * GATES];     // precomputed input-gate contributions, 16 MB

// ---------------------------------------------------------------------------
// Phase A: z[s,i] = sum_j W_exp[e(s),i,j]*embs[s,j] + b_exp[e(s),i]
// One block per token; W_exp (3 MB) stays L2-resident.
// ---------------------------------------------------------------------------
__global__ void k_expert(const float* __restrict__ embs,
                         const int* __restrict__ pos_ids,
                         const float* __restrict__ W_exp,
                         const float* __restrict__ b_exp) {
    __shared__ float e_s[DIM];
    int s = blockIdx.x;
    int i = threadIdx.x;
    e_s[i] = embs[s * DIM + i];
    __syncthreads();
    int e = pos_ids[s];
    const float* Wr = W_exp + ((size_t)e * DIM + i) * DIM;
    float acc = b_exp[e * DIM + i];
#pragma unroll
    for (int q = 0; q < DIM / 4; q++) {
        float4 w4 = *reinterpret_cast<const float4*>(Wr + 4 * q);
        acc = fmaf(w4.x, e_s[4 * q + 0], acc);
        acc = fmaf(w4.y, e_s[4 * q + 1], acc);
        acc = fmaf(w4.z, e_s[4 * q + 2], acc);
        acc = fmaf(w4.w, e_s[4 * q + 3], acc);
    }
    g_z[s * DIM + i] = acc;
}

// ---------------------------------------------------------------------------
// Phase B: xg[s,t] = sum_j z[s,j]*W_ih[t,j] + b_ih[t] + b_hh[t]
// Block = 8 tokens x 512 gate rows; W row loaded once, reused for 8 tokens.
// ---------------------------------------------------------------------------
__global__ void k_inproj(const float* __restrict__ W_ih,
                         const float* __restrict__ b_ih,
                         const float* __restrict__ b_hh) {
    __shared__ float z_s[TOK_PER_BLK][DIM];
    int t = threadIdx.x;
    int tok0 = blockIdx.x * TOK_PER_BLK;
    for (int i = t; i < TOK_PER_BLK * DIM; i += GATES)
        z_s[i / DIM][i % DIM] = g_z[tok0 * DIM + i];
    __syncthreads();
    float acc[TOK_PER_BLK];
    float b = b_ih[t] + b_hh[t];
#pragma unroll
    for (int r = 0; r < TOK_PER_BLK; r++) acc[r] = b;
    const float* Wr = W_ih + t * DIM;
#pragma unroll
    for (int q = 0; q < DIM / 4; q++) {
        float4 w4 = *reinterpret_cast<const float4*>(Wr + 4 * q);
#pragma unroll
        for (int r = 0; r < TOK_PER_BLK; r++) {
            acc[r] = fmaf(w4.x, z_s[r][4 * q + 0], acc[r]);
            acc[r] = fmaf(w4.y, z_s[r][4 * q + 1], acc[r]);
            acc[r] = fmaf(w4.z, z_s[r][4 * q + 2], acc[r]);
            acc[r] = fmaf(w4.w, z_s[r][4 * q + 3], acc[r]);
        }
    }
#pragma unroll
    for (int r = 0; r < TOK_PER_BLK; r++)
        g_xg[(size_t)(tok0 + r) * GATES + t] = acc[r];
}

// ---------------------------------------------------------------------------
// Phase C+D: sequential LSTM scan + running max-pool.
// Single persistent 512-thread CTA. Thread t owns gate row t.
// W_hh row t: cols 0..63 in registers (64 regs/thread = 32K regs total),
// cols 64..127 in SMEM at padded stride 68 floats (conflict-free LDS.128).
// ---------------------------------------------------------------------------
__device__ __forceinline__ float fast_sigmoid(float x) {
    return 1.0f / (1.0f + __expf(-x));
}
__device__ __forceinline__ float fast_tanh(float x) {
    // exact at saturation: exp(2x)->inf gives 1, ->0 gives -1
    return 1.0f - 2.0f / (__expf(2.0f * x) + 1.0f);
}

__global__ __launch_bounds__(512, 1) void k_lstm(const float* __restrict__ W_hh,
                                                 float* __restrict__ out) {
    extern __shared__ float sm[];
    float* wsm    = sm;                          // [512][WSM_STRIDE], cols 64..127
    float* gate_s = sm + GATES * WSM_STRIDE;     // [512]
    float* h_s    = gate_s + GATES;              // [128] (+pad)
    int t = threadIdx.x;

    const float* Wr = W_hh + t * DIM;
    float w[64];
#pragma unroll
    for (int q = 0; q < 16; q++) {
        float4 v = *reinterpret_cast<const float4*>(Wr + 4 * q);
        w[4 * q + 0] = v.x; w[4 * q + 1] = v.y;
        w[4 * q + 2] = v.z; w[4 * q + 3] = v.w;
    }
#pragma unroll
    for (int q = 0; q < 16; q++) {
        float4 v = *reinterpret_cast<const float4*>(Wr + 64 + 4 * q);
        *reinterpret_cast<float4*>(wsm + t * WSM_STRIDE + 4 * q) = v;
    }
    if (t < DIM) h_s[t] = 0.0f;

    float c = 0.0f;
    float hmax = -3.0e38f;
    float xg_next = g_xg[t];          // step 0's input contribution
    __syncthreads();

    for (int step = 0; step < SEQ; step++) {
        float acc0 = xg_next;
        float acc1 = 0.0f;
        // prefetch next step's xg a full step (~1200 cyc) ahead of its use
        int nstep = (step < SEQ - 1) ? step + 1 : step;
        xg_next = __ldg(&g_xg[(size_t)nstep * GATES + t]);

        const float* wrow = wsm + t * WSM_STRIDE;
#pragma unroll
        for (int q = 0; q < 16; q++) {
            float4 h4 = *reinterpret_cast<const float4*>(h_s + 4 * q);  // broadcast
            acc0 = fmaf(w[4 * q + 0], h4.x, acc0);
            acc1 = fmaf(w[4 * q + 1], h4.y, acc1);
            acc0 = fmaf(w[4 * q + 2], h4.z, acc0);
            acc1 = fmaf(w[4 * q + 3], h4.w, acc1);
        }
#pragma unroll
        for (int q = 0; q < 16; q++) {
            float4 h4 = *reinterpret_cast<const float4*>(h_s + 64 + 4 * q); // broadcast
            float4 w4 = *reinterpret_cast<const float4*>(wrow + 4 * q);     // conflict-free
            acc0 = fmaf(w4.x, h4.x, acc0);
            acc1 = fmaf(w4.y, h4.y, acc1);
            acc0 = fmaf(w4.z, h4.z, acc0);
            acc1 = fmaf(w4.w, h4.w, acc1);
        }
        gate_s[t] = acc0 + acc1;
        __syncthreads();

        if (t < DIM) {
            float gi = gate_s[t];
            float gf = gate_s[DIM + t];
            float gg = gate_s[2 * DIM + t];
            float go = gate_s[3 * DIM + t];
            float iv = fast_sigmoid(gi);
            float fv = fast_sigmoid(gf);
            float gv = fast_tanh(gg);
            float ov = fast_sigmoid(go);
            c = fmaf(fv, c, iv * gv);
            float h = ov * fast_tanh(c);
            hmax = fmaxf(hmax, h);
            h_s[t] = h;
        }
        __syncthreads();
    }

    if (t < DIM) out[t] = hmax;
}

// ---------------------------------------------------------------------------
extern "C" void kernel_launch(void* const* d_in, const int* in_sizes, int n_in,
                              void* d_out, int out_size) {
    const float* embs  = (const float*)d_in[0];
    const int*   pos   = (const int*)  d_in[1];
    const float* W_exp = (const float*)d_in[2];
    const float* b_exp = (const float*)d_in[3];
    const float* W_ih  = (const float*)d_in[4];
    const float* W_hh  = (const float*)d_in[5];
    const float* b_ih  = (const float*)d_in[6];
    const float* b_hh  = (const float*)d_in[7];
    float* out = (float*)d_out;

    k_expert<<<SEQ, DIM>>>(embs, pos, W_exp, b_exp);
    k_inproj<<<SEQ / TOK_PER_BLK, GATES>>>(W_ih, b_ih, b_hh);

    (void)cudaFuncSetAttribute(k_lstm, cudaFuncAttributeMaxDynamicSharedMemorySize,
                               SMEM_FLOATS * (int)sizeof(float));
    k_lstm<<<1, GATES, SMEM_FLOATS * sizeof(float)>>>(W_hh, out);
}

// round 4
// speedup vs baseline: 1.0917x; 1.0917x over previous
#include <cuda_runtime.h>

#define SEQ   8192
#define DIM   128
#define GATES 512
#define TOK_PER_BLK 8

typedef unsigned long long u64;

// wsm row stride in u64: 32 used pairs + 2 pad = 34 u64 = 68 words.
// LDS.128: quarter-warp (8 lanes) x 16B = 128B; lane t bank-start = (68t+4q)%32
// = (4t+4q)%32 -> 8 distinct 4-bank slices -> conflict-free.
#define WSM_STRIDE_U64 34
#define SMEM_U64 (GATES * WSM_STRIDE_U64 + GATES / 2 + DIM / 2 + 16)

// Scratch (device globals; no runtime allocation allowed)
__device__ float g_z[SEQ * DIM];        // expert-linear output, 4 MB
__device__ float g_xg[SEQ * GATES];     // precomputed input-gate contributions, 16 MB

// ---------------------------------------------------------------------------
// f32x2 packed helpers (FFMA2 is only reachable via PTX fma.rn.f32x2)
// ---------------------------------------------------------------------------
__device__ __forceinline__ u64 fma2(u64 a, u64 b, u64 c) {
    u64 d;
    asm("fma.rn.f32x2 %0, %1, %2, %3;" : "=l"(d) : "l"(a), "l"(b), "l"(c));
    return d;
}
__device__ __forceinline__ u64 add2(u64 a, u64 b) {
    u64 d;
    asm("add.rn.f32x2 %0, %1, %2;" : "=l"(d) : "l"(a), "l"(b));
    return d;
}
__device__ __forceinline__ u64 pack2(float lo, float hi) {
    u64 p;
    asm("mov.b64 %0, {%1, %2};" : "=l"(p) : "r"(__float_as_uint(lo)), "r"(__float_as_uint(hi)));
    return p;
}
__device__ __forceinline__ float hsum2(u64 p) {
    unsigned int lo, hi;
    asm("mov.b64 {%0, %1}, %2;" : "=r"(lo), "=r"(hi) : "l"(p));
    return __uint_as_float(lo) + __uint_as_float(hi);
}

__device__ __forceinline__ float fast_sigmoid(float x) {
    return 1.0f / (1.0f + __expf(-x));
}
__device__ __forceinline__ float fast_tanh(float x) {
    // exact at saturation: exp(2x)->inf gives 1, ->0 gives -1
    return 1.0f - 2.0f / (__expf(2.0f * x) + 1.0f);
}

// ---------------------------------------------------------------------------
// Phase A: z[s,i] = sum_j W_exp[e(s),i,j]*embs[s,j] + b_exp[e(s),i]
// ---------------------------------------------------------------------------
__global__ void k_expert(const float* __restrict__ embs,
                         const int* __restrict__ pos_ids,
                         const float* __restrict__ W_exp,
                         const float* __restrict__ b_exp) {
    __shared__ float e_s[DIM];
    int s = blockIdx.x;
    int i = threadIdx.x;
    e_s[i] = embs[s * DIM + i];
    __syncthreads();
    int e = pos_ids[s];
    const float* Wr = W_exp + ((size_t)e * DIM + i) * DIM;
    float acc = b_exp[e * DIM + i];
#pragma unroll
    for (int q = 0; q < DIM / 4; q++) {
        float4 w4 = *reinterpret_cast<const float4*>(Wr + 4 * q);
        acc = fmaf(w4.x, e_s[4 * q + 0], acc);
        acc = fmaf(w4.y, e_s[4 * q + 1], acc);
        acc = fmaf(w4.z, e_s[4 * q + 2], acc);
        acc = fmaf(w4.w, e_s[4 * q + 3], acc);
    }
    g_z[s * DIM + i] = acc;
}

// ---------------------------------------------------------------------------
// Phase B: xg[s,t] = sum_j z[s,j]*W_ih[t,j] + b_ih[t] + b_hh[t]
// ---------------------------------------------------------------------------
__global__ void k_inproj(const float* __restrict__ W_ih,
                         const float* __restrict__ b_ih,
                         const float* __restrict__ b_hh) {
    __shared__ float z_s[TOK_PER_BLK][DIM];
    int t = threadIdx.x;
    int tok0 = blockIdx.x * TOK_PER_BLK;
    for (int i = t; i < TOK_PER_BLK * DIM; i += GATES)
        z_s[i / DIM][i % DIM] = g_z[tok0 * DIM + i];
    __syncthreads();
    float acc[TOK_PER_BLK];
    float b = b_ih[t] + b_hh[t];
#pragma unroll
    for (int r = 0; r < TOK_PER_BLK; r++) acc[r] = b;
    const float* Wr = W_ih + t * DIM;
#pragma unroll
    for (int q = 0; q < DIM / 4; q++) {
        float4 w4 = *reinterpret_cast<const float4*>(Wr + 4 * q);
#pragma unroll
        for (int r = 0; r < TOK_PER_BLK; r++) {
            acc[r] = fmaf(w4.x, z_s[r][4 * q + 0], acc[r]);
            acc[r] = fmaf(w4.y, z_s[r][4 * q + 1], acc[r]);
            acc[r] = fmaf(w4.z, z_s[r][4 * q + 2], acc[r]);
            acc[r] = fmaf(w4.w, z_s[r][4 * q + 3], acc[r]);
        }
    }
#pragma unroll
    for (int r = 0; r < TOK_PER_BLK; r++)
        g_xg[(size_t)(tok0 + r) * GATES + t] = acc[r];
}

// ---------------------------------------------------------------------------
// Phase C+D: sequential LSTM scan + running max-pool.
// Single persistent 512-thread CTA. Thread t owns gate row t.
// W_hh row t as f32x2 pairs: pairs 0..31 (cols 0..63) in registers,
// pairs 32..63 (cols 64..127) in SMEM (stride 34 u64, conflict-free LDS.128).
// Gate nonlinearity applied 512-wide BEFORE the barrier; the 128-wide serial
// section only does the c/h update (one MUFU chain).
// ---------------------------------------------------------------------------
__global__ __launch_bounds__(512, 1) void k_lstm(const float* __restrict__ W_hh,
                                                 float* __restrict__ out) {
    extern __shared__ u64 sm[];
    u64*   wsm    = sm;                                   // [512][34]
    float* gate_s = (float*)(sm + GATES * WSM_STRIDE_U64); // [512] activated gates
    u64*   h2     = (u64*)(gate_s + GATES);                // [64] = 128 floats
    float* h_f    = (float*)h2;

    int t = threadIdx.x;
    bool is_g = (t >= 2 * DIM) && (t < 3 * DIM);   // gate order: i, f, g, o

    const u64* Wr = reinterpret_cast<const u64*>(W_hh + t * DIM);
    u64 w2[32];
#pragma unroll
    for (int j = 0; j < 32; j++) w2[j] = Wr[j];
    u64* wrow = wsm + t * WSM_STRIDE_U64;
#pragma unroll
    for (int j = 0; j < 16; j++) {
        ulonglong2 v = reinterpret_cast<const ulonglong2*>(Wr + 32)[j];
        reinterpret_cast<ulonglong2*>(wrow)[j] = v;
    }
    if (t < DIM) h_f[t] = 0.0f;

    float c = 0.0f;
    float hmax = -3.0e38f;
    float xg_next = g_xg[t];          // step 0's input contribution
    __syncthreads();

    for (int step = 0; step < SEQ; step++) {
        u64 acc0 = pack2(xg_next, 0.0f);
        u64 acc1 = pack2(0.0f, 0.0f);
        // prefetch next step's xg a full step ahead of its use
        int nstep = min(step + 1, SEQ - 1);
        xg_next = __ldg(&g_xg[(size_t)nstep * GATES + t]);

#pragma unroll
        for (int q = 0; q < 16; q++) {
            ulonglong2 h4 = reinterpret_cast<const ulonglong2*>(h2)[q];  // broadcast
            acc0 = fma2(w2[2 * q + 0], h4.x, acc0);
            acc1 = fma2(w2[2 * q + 1], h4.y, acc1);
        }
#pragma unroll
        for (int q = 0; q < 16; q++) {
            ulonglong2 h4 = reinterpret_cast<const ulonglong2*>(h2 + 32)[q]; // broadcast
            ulonglong2 w4 = reinterpret_cast<const ulonglong2*>(wrow)[q];    // conflict-free
            acc0 = fma2(w4.x, h4.x, acc0);
            acc1 = fma2(w4.y, h4.y, acc1);
        }
        float v = hsum2(add2(acc0, acc1));
        // apply this gate's nonlinearity 512-wide (off the serial path)
        gate_s[t] = is_g ? fast_tanh(v) : fast_sigmoid(v);
        __syncthreads();

        if (t < DIM) {
            float iv = gate_s[t];
            float fv = gate_s[DIM + t];
            float gv = gate_s[2 * DIM + t];
            float ov = gate_s[3 * DIM + t];
            c = fmaf(fv, c, iv * gv);
            float h = ov * fast_tanh(c);
            hmax = fmaxf(hmax, h);
            h_f[t] = h;
        }
        __syncthreads();
    }

    if (t < DIM) out[t] = hmax;
}

// ---------------------------------------------------------------------------
extern "C" void kernel_launch(void* const* d_in, const int* in_sizes, int n_in,
                              void* d_out, int out_size) {
    const float* embs  = (const float*)d_in[0];
    const int*   pos   = (const int*)  d_in[1];
    const float* W_exp = (const float*)d_in[2];
    const float* b_exp = (const float*)d_in[3];
    const float* W_ih  = (const float*)d_in[4];
    const float* W_hh  = (const float*)d_in[5];
    const float* b_ih  = (const float*)d_in[6];
    const float* b_hh  = (const float*)d_in[7];
    float* out = (float*)d_out;

    k_expert<<<SEQ, DIM>>>(embs, pos, W_exp, b_exp);
    k_inproj<<<SEQ / TOK_PER_BLK, GATES>>>(W_ih, b_ih, b_hh);

    (void)cudaFuncSetAttribute(k_lstm, cudaFuncAttributeMaxDynamicSharedMemorySize,
                               SMEM_U64 * (int)sizeof(u64));
    k_lstm<<<1, GATES, SMEM_U64 * sizeof(u64)>>>(W_hh, out);
}

// round 8
// speedup vs baseline: 1.4778x; 1.3537x over previous
#include <cuda_runtime.h>
#include <cstdint>

#define SEQ   8192
#define DIM   128
#define GATES 512
#define TOK_PER_BLK 8
#define ROWS_PER_CTA 256
#define LSTM_THREADS 256

typedef unsigned long long u64;

// Scratch (device globals; no runtime allocation allowed)
__device__ float g_z[SEQ * DIM];        // expert-linear output, 4 MB
__device__ float g_xg[SEQ * GATES];     // precomputed input-gate contributions, 16 MB

// ---------------------------------------------------------------------------
// f32x2 packed helpers (FFMA2 only reachable via PTX fma.rn.f32x2)
// ---------------------------------------------------------------------------
__device__ __forceinline__ u64 fma2(u64 a, u64 b, u64 c) {
    u64 d;
    asm("fma.rn.f32x2 %0, %1, %2, %3;" : "=l"(d) : "l"(a), "l"(b), "l"(c));
    return d;
}
__device__ __forceinline__ u64 add2(u64 a, u64 b) {
    u64 d;
    asm("add.rn.f32x2 %0, %1, %2;" : "=l"(d) : "l"(a), "l"(b));
    return d;
}
__device__ __forceinline__ u64 pack2(float lo, float hi) {
    u64 p;
    asm("mov.b64 %0, {%1, %2};" : "=l"(p) : "r"(__float_as_uint(lo)), "r"(__float_as_uint(hi)));
    return p;
}
__device__ __forceinline__ float hsum2(u64 p) {
    unsigned int lo, hi;
    asm("mov.b64 {%0, %1}, %2;" : "=r"(lo), "=r"(hi) : "l"(p));
    return __uint_as_float(lo) + __uint_as_float(hi);
}

__device__ __forceinline__ float fast_sigmoid(float x) {
    return 1.0f / (1.0f + __expf(-x));
}
__device__ __forceinline__ float fast_tanh(float x) {
    // exact at saturation: exp(2x)->inf gives 1, ->0 gives -1
    return 1.0f - 2.0f / (__expf(2.0f * x) + 1.0f);
}

// ---------------------------------------------------------------------------
// Cluster / mbarrier primitives
// ---------------------------------------------------------------------------
__device__ __forceinline__ uint32_t smem_u32(const void* p) {
    uint32_t a;
    asm("{ .reg .u64 t; cvta.to.shared.u64 t, %1; cvt.u32.u64 %0, t; }"
        : "=r"(a) : "l"(p));
    return a;
}
__device__ __forceinline__ uint32_t ctarank() {
    uint32_t r;
    asm("mov.u32 %0, %%cluster_ctarank;" : "=r"(r));
    return r;
}
__device__ __forceinline__ uint32_t mapa_u32(uint32_t addr, uint32_t rank) {
    uint32_t r;
    asm("mapa.shared::cluster.u32 %0, %1, %2;" : "=r"(r) : "r"(addr), "r"(rank));
    return r;
}
__device__ __forceinline__ void st_cluster_f32(uint32_t addr, float v) {
    asm volatile("st.shared::cluster.b32 [%0], %1;"
                 :: "r"(addr), "r"(__float_as_uint(v)) : "memory");
}
__device__ __forceinline__ void mbar_init(uint32_t bar, uint32_t cnt) {
    asm volatile("mbarrier.init.shared.b64 [%0], %1;" :: "r"(bar), "r"(cnt) : "memory");
}
// release.cluster: orders the preceding st.shared::cluster before the arrival
__device__ __forceinline__ void mbar_arrive_release_cluster(uint32_t bar) {
    asm volatile("mbarrier.arrive.release.cluster.shared::cluster.b64 _, [%0];"
                 :: "r"(bar) : "memory");
}
__device__ __forceinline__ void mbar_wait_parity_cluster(uint32_t bar, uint32_t parity) {
    uint32_t done;
    do {
        asm volatile(
            "{\n\t.reg .pred p;\n\t"
            "mbarrier.try_wait.parity.acquire.cluster.shared::cta.b64 p, [%1], %2;\n\t"
            "selp.b32 %0, 1, 0, p;\n\t}"
            : "=r"(done) : "r"(bar), "r"(parity) : "memory");
    } while (!done);
}
__device__ __forceinline__ void cluster_sync() {
    asm volatile("barrier.cluster.arrive.aligned;" ::: "memory");
    asm volatile("barrier.cluster.wait.aligned;" ::: "memory");
}

// ---------------------------------------------------------------------------
// Phase A: z[s,i] = sum_j W_exp[e(s),i,j]*embs[s,j] + b_exp[e(s),i]
// ---------------------------------------------------------------------------
__global__ void k_expert(const float* __restrict__ embs,
                         const int* __restrict__ pos_ids,
                         const float* __restrict__ W_exp,
                         const float* __restrict__ b_exp) {
    __shared__ float e_s[DIM];
    int s = blockIdx.x;
    int i = threadIdx.x;
    e_s[i] = embs[s * DIM + i];
    __syncthreads();
    int e = pos_ids[s];
    const float* Wr = W_exp + ((size_t)e * DIM + i) * DIM;
    float acc = b_exp[e * DIM + i];
#pragma unroll
    for (int q = 0; q < DIM / 4; q++) {
        float4 w4 = *reinterpret_cast<const float4*>(Wr + 4 * q);
        acc = fmaf(w4.x, e_s[4 * q + 0], acc);
        acc = fmaf(w4.y, e_s[4 * q + 1], acc);
        acc = fmaf(w4.z, e_s[4 * q + 2], acc);
        acc = fmaf(w4.w, e_s[4 * q + 3], acc);
    }
    g_z[s * DIM + i] = acc;
}

// ---------------------------------------------------------------------------
// Phase B: xg[s,t] = sum_j z[s,j]*W_ih[t,j] + b_ih[t] + b_hh[t]
// ---------------------------------------------------------------------------
__global__ void k_inproj(const float* __restrict__ W_ih,
                         const float* __restrict__ b_ih,
                         const float* __restrict__ b_hh) {
    __shared__ float z_s[TOK_PER_BLK][DIM];
    int t = threadIdx.x;
    int tok0 = blockIdx.x * TOK_PER_BLK;
    for (int i = t; i < TOK_PER_BLK * DIM; i += GATES)
        z_s[i / DIM][i % DIM] = g_z[tok0 * DIM + i];
    __syncthreads();
    float acc[TOK_PER_BLK];
    float b = b_ih[t] + b_hh[t];
#pragma unroll
    for (int r = 0; r < TOK_PER_BLK; r++) acc[r] = b;
    const float* Wr = W_ih + t * DIM;
#pragma unroll
    for (int q = 0; q < DIM / 4; q++) {
        float4 w4 = *reinterpret_cast<const float4*>(Wr + 4 * q);
#pragma unroll
        for (int r = 0; r < TOK_PER_BLK; r++) {
            acc[r] = fmaf(w4.x, z_s[r][4 * q + 0], acc[r]);
            acc[r] = fmaf(w4.y, z_s[r][4 * q + 1], acc[r]);
            acc[r] = fmaf(w4.z, z_s[r][4 * q + 2], acc[r]);
            acc[r] = fmaf(w4.w, z_s[r][4 * q + 3], acc[r]);
        }
    }
#pragma unroll
    for (int r = 0; r < TOK_PER_BLK; r++)
        g_xg[(size_t)(tok0 + r) * GATES + t] = acc[r];
}

// ---------------------------------------------------------------------------
// Phase C+D: LSTM scan on a 2-CTA cluster. CTA rank r owns gate rows
// [256r, 256r+256): one full W_hh row per thread, entirely in registers
// (64 u64 = 128 regs). Zero W SMEM traffic. Each step:
//   GEMV(regs x h-broadcast) -> activation -> gate to local smem + peer smem
//   (st.shared::cluster, double-buffered) -> arrive on peer mbarrier ->
//   wait own mbarrier (256 peer arrivals) -> both CTAs redundantly update
//   c/h (identical fp) -> no h exchange needed.
// ---------------------------------------------------------------------------
__global__ __cluster_dims__(2, 1, 1) __launch_bounds__(LSTM_THREADS, 1)
void k_lstm2(const float* __restrict__ W_hh, float* __restrict__ out) {
    __shared__ __align__(16) u64 h2[DIM / 2];          // h as 64 f32x2 pairs
    __shared__ __align__(16) float gate_s[2][GATES];   // double-buffered gates
    __shared__ __align__(8) u64 mbar;
    float* h_f = (float*)h2;

    int t = threadIdx.x;
    uint32_t rank = ctarank();
    uint32_t peer = rank ^ 1u;
    int row = (int)rank * ROWS_PER_CTA + t;
    bool is_g = (rank == 1) && (t < DIM);   // rows 256..383 = g gate (tanh)

    // W_hh row fully in registers
    u64 w2[64];
    const u64* Wr = reinterpret_cast<const u64*>(W_hh + (size_t)row * DIM);
#pragma unroll
    for (int j = 0; j < 64; j++) w2[j] = Wr[j];

    uint32_t bar = smem_u32(&mbar);
    if (t == 0) mbar_init(bar, ROWS_PER_CTA);   // 256 arrivals from peer per step
    if (t < DIM) h_f[t] = 0.0f;
    __syncthreads();
    cluster_sync();   // both CTAs' barriers initialized before any remote arrive

    // precompute remote addresses
    uint32_t rbar = mapa_u32(bar, peer);
    uint32_t rg0  = mapa_u32(smem_u32(&gate_s[0][row]), peer);
    uint32_t rg1  = mapa_u32(smem_u32(&gate_s[1][row]), peer);

    float c = 0.0f;
    float hmax = -3.0e38f;
    float xg_next = g_xg[row];   // step 0's input contribution

    for (int step = 0; step < SEQ; step++) {
        int buf = step & 1;
        u64 a0 = pack2(xg_next, 0.0f);
        u64 a1 = pack2(0.0f, 0.0f);
        u64 a2 = a1, a3 = a1;
        int nstep = min(step + 1, SEQ - 1);
        xg_next = __ldg(&g_xg[(size_t)nstep * GATES + row]);

        const ulonglong2* hh = reinterpret_cast<const ulonglong2*>(h2);
#pragma unroll
        for (int q = 0; q < 16; q++) {
            ulonglong2 p0 = hh[2 * q];       // broadcast LDS
            ulonglong2 p1 = hh[2 * q + 1];
            a0 = fma2(w2[4 * q + 0], p0.x, a0);
            a1 = fma2(w2[4 * q + 1], p0.y, a1);
            a2 = fma2(w2[4 * q + 2], p1.x, a2);
            a3 = fma2(w2[4 * q + 3], p1.y, a3);
        }
        float v = hsum2(add2(add2(a0, a1), add2(a2, a3)));
        float gv = is_g ? fast_tanh(v) : fast_sigmoid(v);

        gate_s[buf][row] = gv;                       // local copy
        st_cluster_f32(buf ? rg1 : rg0, gv);         // peer copy
        mbar_arrive_release_cluster(rbar);           // signal peer

        mbar_wait_parity_cluster(bar, step & 1);     // wait peer's 256 gates
        __syncthreads();                             // local gates visible + all waited

        if (t < DIM) {
            float iv = gate_s[buf][t];
            float fv = gate_s[buf][DIM + t];
            float gg = gate_s[buf][2 * DIM + t];
            float ov = gate_s[buf][3 * DIM + t];
            c = fmaf(fv, c, iv * gg);
            float h = ov * fast_tanh(c);
            hmax = fmaxf(hmax, h);
            h_f[t] = h;                              // redundant in both CTAs
        }
        __syncthreads();
    }

    if (rank == 0 && t < DIM) out[t] = hmax;
    cluster_sync();   // keep peer smem alive until all remote ops drained
}

// ---------------------------------------------------------------------------
extern "C" void kernel_launch(void* const* d_in, const int* in_sizes, int n_in,
                              void* d_out, int out_size) {
    const float* embs  = (const float*)d_in[0];
    const int*   pos   = (const int*)  d_in[1];
    const float* W_exp = (const float*)d_in[2];
    const float* b_exp = (const float*)d_in[3];
    const float* W_ih  = (const float*)d_in[4];
    const float* W_hh  = (const float*)d_in[5];
    const float* b_ih  = (const float*)d_in[6];
    const float* b_hh  = (const float*)d_in[7];
    float* out = (float*)d_out;

    k_expert<<<SEQ, DIM>>>(embs, pos, W_exp, b_exp);
    k_inproj<<<SEQ / TOK_PER_BLK, GATES>>>(W_ih, b_ih, b_hh);
    k_lstm2<<<2, LSTM_THREADS>>>(W_hh, out);
}